// round 6
// baseline (speedup 1.0000x reference)
#include <cuda_runtime.h>

// CumulantSOAP: per-column mean/var of X (200000 x 576 f32) -> (cum - mu) @ W (1728x4) -> 4 floats.
// Single pass (S1, S2); mom1 treated as 0 (pure fp rounding residual). Deterministic.
//
// R6: stage-2 fix. R5's 21.9us K2 was __ldcv serialization (volatile loads can't batch:
// 148 x 250cyc ~ 24us on one SM). Now: 148 blocks x 576 thr, coalesced __ldcg everywhere,
// final last-block uses batchable loads with unroll-8 MLP. K1 unchanged (~66us, 84% DRAM).

#define NROWS   200000
#define PCOLS   576
#define PV      144                       // float4 groups per row
#define TOTALV  ((size_t)NROWS * PV)      // 28,800,000 float4
#define BLK1    288
#define G1      740
#define G2      148
#define RPB     5                         // G1 / G2

__device__ float g_s1[(size_t)G1 * PCOLS];   // [block][col] partial sum x
__device__ float g_s2[(size_t)G1 * PCOLS];   // [block][col] partial sum x^2
__device__ float g_t1[(size_t)G2 * PCOLS];   // [k2block][col]
__device__ float g_t2[(size_t)G2 * PCOLS];
__device__ int   g_count = 0;

// -------------------- Stage 1 (unchanged from R5) --------------------
__global__ __launch_bounds__(BLK1, 6) void k1_colsums(const float* __restrict__ X) {
    const float4* __restrict__ Xv = reinterpret_cast<const float4*>(X);
    const int tid = threadIdx.x;

    float s1x = 0.f, s1y = 0.f, s1z = 0.f, s1w = 0.f;
    float s2x = 0.f, s2y = 0.f, s2z = 0.f, s2w = 0.f;

    size_t i = (size_t)blockIdx.x * BLK1 + tid;
    const size_t stride = (size_t)G1 * BLK1;   // 213120, divisible by 144

    for (; i + 3 * stride < TOTALV; i += 4 * stride) {
        float4 a = __ldcs(Xv + i);
        float4 b = __ldcs(Xv + i + stride);
        float4 c = __ldcs(Xv + i + 2 * stride);
        float4 d = __ldcs(Xv + i + 3 * stride);

        s1x += a.x; s1y += a.y; s1z += a.z; s1w += a.w;
        s2x = fmaf(a.x, a.x, s2x); s2y = fmaf(a.y, a.y, s2y);
        s2z = fmaf(a.z, a.z, s2z); s2w = fmaf(a.w, a.w, s2w);

        s1x += b.x; s1y += b.y; s1z += b.z; s1w += b.w;
        s2x = fmaf(b.x, b.x, s2x); s2y = fmaf(b.y, b.y, s2y);
        s2z = fmaf(b.z, b.z, s2z); s2w = fmaf(b.w, b.w, s2w);

        s1x += c.x; s1y += c.y; s1z += c.z; s1w += c.w;
        s2x = fmaf(c.x, c.x, s2x); s2y = fmaf(c.y, c.y, s2y);
        s2z = fmaf(c.z, c.z, s2z); s2w = fmaf(c.w, c.w, s2w);

        s1x += d.x; s1y += d.y; s1z += d.z; s1w += d.w;
        s2x = fmaf(d.x, d.x, s2x); s2y = fmaf(d.y, d.y, s2y);
        s2z = fmaf(d.z, d.z, s2z); s2w = fmaf(d.w, d.w, s2w);
    }
    for (; i < TOTALV; i += stride) {
        float4 a = __ldcs(Xv + i);
        s1x += a.x; s1y += a.y; s1z += a.z; s1w += a.w;
        s2x = fmaf(a.x, a.x, s2x); s2y = fmaf(a.y, a.y, s2y);
        s2z = fmaf(a.z, a.z, s2z); s2w = fmaf(a.w, a.w, s2w);
    }

    __shared__ float red[PV][8];
    if (tid >= PV) {
        float* r = red[tid - PV];
        r[0] = s1x; r[1] = s1y; r[2] = s1z; r[3] = s1w;
        r[4] = s2x; r[5] = s2y; r[6] = s2z; r[7] = s2w;
    }
    __syncthreads();
    if (tid < PV) {
        const float* r = red[tid];
        float4 o1 = make_float4(s1x + r[0], s1y + r[1], s1z + r[2], s1w + r[3]);
        float4 o2 = make_float4(s2x + r[4], s2y + r[5], s2z + r[6], s2w + r[7]);
        reinterpret_cast<float4*>(g_s1)[(size_t)blockIdx.x * PV + tid] = o1;
        reinterpret_cast<float4*>(g_s2)[(size_t)blockIdx.x * PV + tid] = o2;
    }
}

__device__ __forceinline__ float4 f4add(float4 a, float4 b) {
    return make_float4(a.x + b.x, a.y + b.y, a.z + b.z, a.w + b.w);
}

// -------- Stage 2: wide coalesced reduce + fused last-block projection --------
__global__ __launch_bounds__(576) void k2_project(const float* __restrict__ mu,
                                                  const float* __restrict__ W,
                                                  float* __restrict__ out) {
    const int tid = threadIdx.x;
    const int g = tid % PV;            // float4 column group
    const int a = (tid / PV) & 1;      // 0 -> s1, 1 -> s2
    const int p = tid / (2 * PV);      // row phase 0..1

    __shared__ float4 sph[2][2][PV];   // [p][a][g]
    __shared__ int s_last;

    // ---- phase a: reduce 5 rows -> 1, all loads coalesced ----
    {
        const float4* __restrict__ src =
            reinterpret_cast<const float4*>(a ? g_s2 : g_s1);
        const int rbase = blockIdx.x * RPB;
        float4 acc = make_float4(0.f, 0.f, 0.f, 0.f);
        #pragma unroll
        for (int r = p; r < RPB; r += 2)     // p0: 0,2,4  p1: 1,3
            acc = f4add(acc, __ldcg(src + (size_t)(rbase + r) * PV + g));
        sph[p][a][g] = acc;
    }
    __syncthreads();
    if (p == 0) {
        float4 o = f4add(sph[0][a][g], sph[1][a][g]);
        float4* dst = reinterpret_cast<float4*>(a ? g_t2 : g_t1);
        dst[(size_t)blockIdx.x * PV + g] = o;
    }
    __threadfence();
    __syncthreads();
    if (tid == 0) s_last = (atomicAdd(&g_count, 1) == G2 - 1);
    __syncthreads();
    if (!s_last) return;
    __threadfence();

    // ---- final block: reduce 148 rows (batchable __ldcg, MLP 8), project ----
    {
        const float4* __restrict__ tsrc =
            reinterpret_cast<const float4*>(a ? g_t2 : g_t1);
        float4 facc = make_float4(0.f, 0.f, 0.f, 0.f);
        #pragma unroll 8
        for (int r = p; r < G2; r += 2)      // 74 loads per thread
            facc = f4add(facc, __ldcg(tsrc + (size_t)r * PV + g));
        sph[p][a][g] = facc;
    }
    __syncthreads();

    __shared__ float4 stot[2][PV];     // [a][g] : full S1 / S2
    if (p == 0)
        stot[a][g] = f4add(sph[0][a][g], sph[1][a][g]);
    __syncthreads();

    __shared__ float sred[PV][4];
    if (tid < PV) {
        const float invN = 1.0f / (float)NROWS;
        float4 S1 = stot[0][tid];
        float4 S2 = stot[1][tid];
        float s1c[4] = {S1.x, S1.y, S1.z, S1.w};
        float s2c[4] = {S2.x, S2.y, S2.z, S2.w};
        float acc[4] = {0.f, 0.f, 0.f, 0.f};
        #pragma unroll
        for (int c = 0; c < 4; c++) {
            int col  = 4 * tid + c;
            int base = 3 * col;
            float m    = s1c[c] * invN;
            float mom2 = fmaf(-m, m, s2c[c] * invN);   // E[x^2] - m^2
            float c0 = m    - __ldg(mu + base);
            float c1 =      - __ldg(mu + base + 1);    // mom1 ~ 0
            float c2 = mom2 - __ldg(mu + base + 2);
            #pragma unroll
            for (int k = 0; k < 4; k++) {
                float w0 = __ldg(W + (base    ) * 4 + k);
                float w1 = __ldg(W + (base + 1) * 4 + k);
                float w2 = __ldg(W + (base + 2) * 4 + k);
                acc[k] = fmaf(c0, w0, fmaf(c1, w1, fmaf(c2, w2, acc[k])));
            }
        }
        #pragma unroll
        for (int k = 0; k < 4; k++) sred[tid][k] = acc[k];
    }
    __syncthreads();
    if (tid < 64) {
        #pragma unroll
        for (int k = 0; k < 4; k++) {
            float v = sred[tid][k] + sred[tid + 64][k];
            if (tid < 16) v += sred[tid + 128][k];
            sred[tid][k] = v;
        }
    }
    __syncthreads();
    if (tid < 32) {
        #pragma unroll
        for (int k = 0; k < 4; k++) sred[tid][k] += sred[tid + 32][k];
    }
    __syncthreads();
    if (tid < 4) {
        float v = 0.f;
        #pragma unroll
        for (int j = 0; j < 32; j++) v += sred[j][tid];
        out[tid] = v;
    }
    if (tid == 0) g_count = 0;   // reset for next graph replay
}

extern "C" void kernel_launch(void* const* d_in, const int* in_sizes, int n_in,
                              void* d_out, int out_size) {
    const float* X  = (const float*)d_in[0];
    const float* mu = (const float*)d_in[1];
    const float* W  = (const float*)d_in[2];
    float* out = (float*)d_out;

    k1_colsums<<<G1, BLK1>>>(X);
    k2_project<<<G2, 576>>>(mu, W, out);
}

// round 10
// speedup vs baseline: 1.1580x; 1.1580x over previous
#include <cuda_runtime.h>

// CumulantSOAP: per-column mean/var of X (200000 x 576 f32) -> (cum - mu) @ W (1728x4) -> 4 floats.
// Single pass (S1, S2); mom1 treated as 0 (pure fp rounding residual). Deterministic.
//
// R7: stage-2 = ONE fused kernel, 37 blocks x 576 thr. Lessons from R4-R6: the last block's
// private read is ~10x/byte vs grid-wide reduction, and the same-address atomic chain costs
// ~27cyc/block. So: 37 blocks reduce 740->37 rows (coalesced, 10 unrolled loads/thread),
// last block reads only 170KB (37x2 rows), atomic chain 37 long. K1 reverted to plain
// launch_bounds(288) (best measured config, ~66-70us at 84% DRAM).

#define NROWS   200000
#define PCOLS   576
#define PV      144                       // float4 groups per row
#define TOTALV  ((size_t)NROWS * PV)      // 28,800,000 float4
#define BLK1    288
#define G1      740
#define T2B     37
#define CH2     20                        // G1 / T2B

__device__ float g_s1[(size_t)G1 * PCOLS];   // [block][col] partial sum x
__device__ float g_s2[(size_t)G1 * PCOLS];   // [block][col] partial sum x^2
__device__ float g_t1[(size_t)T2B * PCOLS];  // [k2block][col]
__device__ float g_t2[(size_t)T2B * PCOLS];
__device__ int   g_count = 0;

// -------------------- Stage 1 (R2 config: best measured) --------------------
__global__ __launch_bounds__(BLK1) void k1_colsums(const float* __restrict__ X) {
    const float4* __restrict__ Xv = reinterpret_cast<const float4*>(X);
    const int tid = threadIdx.x;

    float s1x = 0.f, s1y = 0.f, s1z = 0.f, s1w = 0.f;
    float s2x = 0.f, s2y = 0.f, s2z = 0.f, s2w = 0.f;

    size_t i = (size_t)blockIdx.x * BLK1 + tid;
    const size_t stride = (size_t)G1 * BLK1;   // 213120, divisible by 144

    for (; i + 3 * stride < TOTALV; i += 4 * stride) {
        float4 a = __ldcs(Xv + i);
        float4 b = __ldcs(Xv + i + stride);
        float4 c = __ldcs(Xv + i + 2 * stride);
        float4 d = __ldcs(Xv + i + 3 * stride);

        s1x += a.x; s1y += a.y; s1z += a.z; s1w += a.w;
        s2x = fmaf(a.x, a.x, s2x); s2y = fmaf(a.y, a.y, s2y);
        s2z = fmaf(a.z, a.z, s2z); s2w = fmaf(a.w, a.w, s2w);

        s1x += b.x; s1y += b.y; s1z += b.z; s1w += b.w;
        s2x = fmaf(b.x, b.x, s2x); s2y = fmaf(b.y, b.y, s2y);
        s2z = fmaf(b.z, b.z, s2z); s2w = fmaf(b.w, b.w, s2w);

        s1x += c.x; s1y += c.y; s1z += c.z; s1w += c.w;
        s2x = fmaf(c.x, c.x, s2x); s2y = fmaf(c.y, c.y, s2y);
        s2z = fmaf(c.z, c.z, s2z); s2w = fmaf(c.w, c.w, s2w);

        s1x += d.x; s1y += d.y; s1z += d.z; s1w += d.w;
        s2x = fmaf(d.x, d.x, s2x); s2y = fmaf(d.y, d.y, s2y);
        s2z = fmaf(d.z, d.z, s2z); s2w = fmaf(d.w, d.w, s2w);
    }
    for (; i < TOTALV; i += stride) {
        float4 a = __ldcs(Xv + i);
        s1x += a.x; s1y += a.y; s1z += a.z; s1w += a.w;
        s2x = fmaf(a.x, a.x, s2x); s2y = fmaf(a.y, a.y, s2y);
        s2z = fmaf(a.z, a.z, s2z); s2w = fmaf(a.w, a.w, s2w);
    }

    __shared__ float red[PV][8];
    if (tid >= PV) {
        float* r = red[tid - PV];
        r[0] = s1x; r[1] = s1y; r[2] = s1z; r[3] = s1w;
        r[4] = s2x; r[5] = s2y; r[6] = s2z; r[7] = s2w;
    }
    __syncthreads();
    if (tid < PV) {
        const float* r = red[tid];
        float4 o1 = make_float4(s1x + r[0], s1y + r[1], s1z + r[2], s1w + r[3]);
        float4 o2 = make_float4(s2x + r[4], s2y + r[5], s2z + r[6], s2w + r[7]);
        reinterpret_cast<float4*>(g_s1)[(size_t)blockIdx.x * PV + tid] = o1;
        reinterpret_cast<float4*>(g_s2)[(size_t)blockIdx.x * PV + tid] = o2;
    }
}

__device__ __forceinline__ float4 f4add(float4 a, float4 b) {
    return make_float4(a.x + b.x, a.y + b.y, a.z + b.z, a.w + b.w);
}

// -------- Stage 2: 37-block reduce + small fused last-block projection --------
__global__ __launch_bounds__(576) void k2_project(const float* __restrict__ mu,
                                                  const float* __restrict__ W,
                                                  float* __restrict__ out) {
    const int tid = threadIdx.x;
    const int g = tid % PV;            // float4 column group
    const int q = tid / PV;            // 0..3
    const int a = q & 1;               // 0 -> s1, 1 -> s2
    const int p = q >> 1;              // row phase 0..1

    __shared__ float4 sph[2][2][PV];   // [p][a][g]
    __shared__ int s_last;

    // ---- phase a: reduce 20 rows -> 1 (10 independent coalesced loads/thread) ----
    {
        const float4* __restrict__ src =
            reinterpret_cast<const float4*>(a ? g_s2 : g_s1);
        const size_t rb = (size_t)blockIdx.x * CH2 + p;
        float4 acc = make_float4(0.f, 0.f, 0.f, 0.f);
        #pragma unroll
        for (int i = 0; i < CH2 / 2; i++)            // rows p, p+2, ..., p+18
            acc = f4add(acc, __ldcg(src + (rb + 2 * i) * PV + g));
        sph[p][a][g] = acc;
    }
    __syncthreads();
    if (p == 0) {
        float4 o = f4add(sph[0][a][g], sph[1][a][g]);
        float4* dst = reinterpret_cast<float4*>(a ? g_t2 : g_t1);
        dst[(size_t)blockIdx.x * PV + g] = o;
    }
    __threadfence();
    __syncthreads();
    if (tid == 0) s_last = (atomicAdd(&g_count, 1) == T2B - 1);
    __syncthreads();
    if (!s_last) return;
    __threadfence();

    // ---- last block: reduce 37 rows x 2 arrays (170 KB), project ----
    {
        const float4* __restrict__ tsrc =
            reinterpret_cast<const float4*>(a ? g_t2 : g_t1);
        float4 e0 = make_float4(0.f, 0.f, 0.f, 0.f);
        float4 e1 = make_float4(0.f, 0.f, 0.f, 0.f);
        // rows p, p+2, ... < 37 ; two independent accumulator chains
        #pragma unroll
        for (int i = 0; i < 9; i++) {
            e0 = f4add(e0, __ldcg(tsrc + (size_t)(p + 4 * i)     * PV + g));
            e1 = f4add(e1, __ldcg(tsrc + (size_t)(p + 4 * i + 2) * PV + g));
        }
        if (p == 0)  // row 36 (even phase only)
            e0 = f4add(e0, __ldcg(tsrc + (size_t)36 * PV + g));
        sph[p][a][g] = f4add(e0, e1);
    }
    __syncthreads();

    __shared__ float4 stot[2][PV];     // [a][g] : full S1 / S2
    if (p == 0)
        stot[a][g] = f4add(sph[0][a][g], sph[1][a][g]);
    __syncthreads();

    __shared__ float sred[PV][4];
    if (tid < PV) {
        const float invN = 1.0f / (float)NROWS;
        float4 S1 = stot[0][tid];
        float4 S2 = stot[1][tid];
        float s1c[4] = {S1.x, S1.y, S1.z, S1.w};
        float s2c[4] = {S2.x, S2.y, S2.z, S2.w};
        float acc[4] = {0.f, 0.f, 0.f, 0.f};
        #pragma unroll
        for (int c = 0; c < 4; c++) {
            int col  = 4 * tid + c;
            int base = 3 * col;
            float m    = s1c[c] * invN;
            float mom2 = fmaf(-m, m, s2c[c] * invN);   // E[x^2] - m^2
            float c0 = m    - __ldg(mu + base);
            float c1 =      - __ldg(mu + base + 1);    // mom1 ~ 0
            float c2 = mom2 - __ldg(mu + base + 2);
            #pragma unroll
            for (int k = 0; k < 4; k++) {
                float w0 = __ldg(W + (base    ) * 4 + k);
                float w1 = __ldg(W + (base + 1) * 4 + k);
                float w2 = __ldg(W + (base + 2) * 4 + k);
                acc[k] = fmaf(c0, w0, fmaf(c1, w1, fmaf(c2, w2, acc[k])));
            }
        }
        #pragma unroll
        for (int k = 0; k < 4; k++) sred[tid][k] = acc[k];
    }
    __syncthreads();
    if (tid < 64) {
        #pragma unroll
        for (int k = 0; k < 4; k++) {
            float v = sred[tid][k] + sred[tid + 64][k];
            if (tid < 16) v += sred[tid + 128][k];
            sred[tid][k] = v;
        }
    }
    __syncthreads();
    if (tid < 32) {
        #pragma unroll
        for (int k = 0; k < 4; k++) sred[tid][k] += sred[tid + 32][k];
    }
    __syncthreads();
    if (tid < 4) {
        float v = 0.f;
        #pragma unroll
        for (int j = 0; j < 32; j++) v += sred[j][tid];
        out[tid] = v;
    }
    if (tid == 0) g_count = 0;   // reset for next graph replay
}

extern "C" void kernel_launch(void* const* d_in, const int* in_sizes, int n_in,
                              void* d_out, int out_size) {
    const float* X  = (const float*)d_in[0];
    const float* mu = (const float*)d_in[1];
    const float* W  = (const float*)d_in[2];
    float* out = (float*)d_out;

    k1_colsums<<<G1, BLK1>>>(X);
    k2_project<<<T2B, 576>>>(mu, W, out);
}